// round 4
// baseline (speedup 1.0000x reference)
#include <cuda_runtime.h>
#include <math.h>

#define NV    65536
#define ITERS 40
#define NF    130050
#define NBLK  256
#define NTHR  512
#define VPB   256                 // vertices per block
#define HALO  257
#define TILE  (VPB + 2*HALO)      // 770 vertices
#define NSYNC 96

// ---- device scratch (no allocations allowed) ----
__device__ __align__(16) float    g_W[NV*7];          // aggregated COO weights (slot 0 = diag)
__device__ __align__(16) float4   g_Z[NV*4];          // Z = Minv*R  (stencil operand)
__device__ __align__(16) float    g_part_d[16*NBLK];  // per-block partials: denom
__device__ __align__(16) float    g_part_r[16*NBLK];  // per-block partials: rz
__device__ unsigned               g_cnt[NSYNC];

// ---------------- helpers ----------------
__device__ __forceinline__ float4 f4mul(float4 a, float4 b){ return make_float4(a.x*b.x,a.y*b.y,a.z*b.z,a.w*b.w); }
__device__ __forceinline__ float4 f4fma(float4 a, float4 b, float4 c){
    return make_float4(fmaf(a.x,b.x,c.x), fmaf(a.y,b.y,c.y), fmaf(a.z,b.z,c.z), fmaf(a.w,b.w,c.w));
}
__device__ __forceinline__ float4 f4fmas(float s, float4 b, float4 c){
    return make_float4(fmaf(s,b.x,c.x), fmaf(s,b.y,c.y), fmaf(s,b.z,c.z), fmaf(s,b.w,c.w));
}
__device__ __forceinline__ float4 f4scale(float s, float4 a){ return make_float4(s*a.x,s*a.y,s*a.z,s*a.w); }
__device__ __forceinline__ float4 f4div_guard(float4 n, float4 d){
    return make_float4(n.x/fmaxf(d.x,1e-30f), n.y/fmaxf(d.y,1e-30f),
                       n.z/fmaxf(d.z,1e-30f), n.w/fmaxf(d.w,1e-30f));
}

// grid barrier: per-index monotone counters, zeroed each launch by zero_k
__device__ __forceinline__ void gsync(int idx){
    __threadfence();                 // order this thread's prior stores to L2
    __syncthreads();
    if (threadIdx.x == 0){
        atomicAdd(&g_cnt[idx], 1u);
        while (*(volatile unsigned*)&g_cnt[idx] < (unsigned)NBLK) { }
        __threadfence();
    }
    __syncthreads();
}

__shared__ __align__(16) float sm_red[16][16];
__shared__ __align__(16) float s_scal[16];      // denom for current iter
__shared__ __align__(16) float s_rzs[2][16];    // rz ring (cur/prev)

// Block partial reduce: each thread holds 8 partials (s[0..1]) for RHS range h*8..h*8+7,
// h == (lane & 1). Result: 16 per-RHS partials STORED to g_part[rhs*NBLK + blockIdx].
__device__ __forceinline__ void block_partials(float4* s, float* gdst){
    #pragma unroll
    for (int m = 2; m < 32; m <<= 1){
        #pragma unroll
        for (int j = 0; j < 2; j++){
            s[j].x += __shfl_xor_sync(0xffffffffu, s[j].x, m);
            s[j].y += __shfl_xor_sync(0xffffffffu, s[j].y, m);
            s[j].z += __shfl_xor_sync(0xffffffffu, s[j].z, m);
            s[j].w += __shfl_xor_sync(0xffffffffu, s[j].w, m);
        }
    }
    int lane = threadIdx.x & 31, wid = threadIdx.x >> 5;
    if (lane < 2){                       // lane0 -> RHS 0..7, lane1 -> RHS 8..15
        float* row = &sm_red[wid][lane*8];
        row[0] = s[0].x; row[1] = s[0].y; row[2] = s[0].z; row[3] = s[0].w;
        row[4] = s[1].x; row[5] = s[1].y; row[6] = s[1].z; row[7] = s[1].w;
    }
    __syncthreads();
    if (threadIdx.x < 16){
        float acc = 0.f;
        #pragma unroll
        for (int w = 0; w < 16; w++) acc += sm_red[w][threadIdx.x];
        gdst[threadIdx.x*NBLK + blockIdx.x] = acc;   // plain store, no atomics
    }
}

// After gsync: every block reduces the 16 rows of g_part (NBLK floats each)
// into dsm[0..15]. Warp w handles RHS w; fully coalesced.
__device__ __forceinline__ void row_reduce(const float* gsrc, float* dsm){
    int wid = threadIdx.x >> 5, lane = threadIdx.x & 31;
    if (wid < 16){
        const float4* p = (const float4*)(gsrc + wid*NBLK) + lane*2;
        float4 a = __ldcg(p);
        float4 b = __ldcg(p+1);
        float acc = (a.x+a.y) + (a.z+a.w) + (b.x+b.y) + (b.z+b.w);
        #pragma unroll
        for (int m = 16; m; m >>= 1) acc += __shfl_xor_sync(0xffffffffu, acc, m);
        if (lane == 0) dsm[wid] = acc;
    }
    __syncthreads();
}

// ---------------- setup kernels ----------------
__global__ void zero_k(){
    int tid = blockIdx.x * blockDim.x + threadIdx.x;   // grid sized to exactly NV*7
    g_W[tid] = 0.f;
    if (tid < NSYNC) g_cnt[tid] = 0u;
}

__global__ void scatter_k(const int* __restrict__ row, const int* __restrict__ col,
                          const float* __restrict__ val, int nnz){
    int e = blockIdx.x * blockDim.x + threadIdx.x;
    if (e >= nnz) return;
    int r = row[e];
    int d = col[e] - r;
    int slot;
    if      (d == 0)    slot = 0;
    else if (d == -256) slot = 1;
    else if (d == 256)  slot = 2;
    else if (d == -1)   slot = 3;
    else if (d == 1)    slot = 4;
    else if (d == -257) slot = 5;
    else if (d == 257)  slot = 6;
    else return;
    atomicAdd(&g_W[r*7 + slot], val[e]);
}

__device__ __forceinline__ float safe_log_neg(float u){
    float us = u;
    if (isnan(us))      us = 1e-9f;
    else if (isinf(us)) us = (us > 0.f) ? 1.0f : 0.0f;
    return -logf(fmaxf(us, 1e-9f));
}

// ---------------- persistent CG + post ----------------
// 2 threads per vertex: h = tid&1 owns RHS [h*8, h*8+8)
__global__ void __launch_bounds__(NTHR, 2)
cg_persist(const float* __restrict__ M, const float* __restrict__ B,
           const float* __restrict__ tp,
           const int* __restrict__ F, const float* __restrict__ gI,
           const float* __restrict__ gJ, const float* __restrict__ gK,
           float* __restrict__ outU, float* __restrict__ outX, float* __restrict__ outS)
{
    extern __shared__ float4 s_tile[];                 // TILE*4 float4 = 49280 B
    const int gtid = blockIdx.x * NTHR + threadIdx.x;  // [0, NV*2)
    const int v = gtid >> 1;
    const int h = gtid & 1;
    const int jb = h * 2;                              // float4 index base within [0,4)
    const int bstart = (blockIdx.x * NTHR) >> 1;       // first vertex of this block
    const int lv = (v - bstart) + HALO;                // this vertex's tile slot
    const float t = *tp;

    float Dw = M[v] + t * g_W[v*7];
    float Minv = 1.0f / fmaxf(Dw, 1e-12f);
    float offW[6];
    #pragma unroll
    for (int e = 0; e < 6; e++) offW[e] = t * g_W[v*7 + 1 + e];

    float4 X[2], R[2], P[2], AP[2], s[2];
    const float4* B4 = (const float4*)B;
    #pragma unroll
    for (int j = 0; j < 2; j++){
        R[j]  = B4[v*4 + jb + j];
        X[j]  = make_float4(0.f,0.f,0.f,0.f);
        float4 z = f4scale(Minv, R[j]);
        __stcg(&g_Z[v*4 + jb + j], z);
        s[j]  = f4mul(R[j], z);
    }
    block_partials(s, g_part_r);
    gsync(0);
    row_reduce(g_part_r, s_rzs[0]);

    const int off[6] = {-256, 256, -1, 1, -257, 257};

    for (int k = 0; k < ITERS; k++){
        // ---- stage Z tile into smem (clamped halo) ----
        #pragma unroll 2
        for (int i = threadIdx.x; i < TILE*4; i += NTHR){
            int vt = bstart - HALO + (i >> 2);
            vt = max(0, min(NV-1, vt));
            s_tile[i] = __ldcg(&g_Z[vt*4 + (i & 3)]);
        }
        __syncthreads();

        // ---- phase 1: P = Z + beta*P ; AP = A*Z + beta*AP ; denom = <P,AP> ----
        {
            float4 z0 = s_tile[lv*4 + jb];
            float4 z1 = s_tile[lv*4 + jb + 1];
            if (k == 0){
                AP[0] = f4scale(Dw, z0);  AP[1] = f4scale(Dw, z1);
                P[0]  = z0;               P[1]  = z1;
            } else {
                const float4* rn = (const float4*)&s_rzs[k & 1][h*8];
                const float4* ro = (const float4*)&s_rzs[(k & 1) ^ 1][h*8];
                float4 bt0 = f4div_guard(rn[0], ro[0]);
                float4 bt1 = f4div_guard(rn[1], ro[1]);
                AP[0] = f4fma(bt0, AP[0], f4scale(Dw, z0));
                AP[1] = f4fma(bt1, AP[1], f4scale(Dw, z1));
                P[0]  = f4fma(bt0, P[0], z0);
                P[1]  = f4fma(bt1, P[1], z1);
            }
        }
        #pragma unroll
        for (int e = 0; e < 6; e++){
            int slot = lv + off[e];
            float w = offW[e];
            float4 z0 = s_tile[slot*4 + jb];
            float4 z1 = s_tile[slot*4 + jb + 1];
            AP[0] = f4fmas(w, z0, AP[0]);
            AP[1] = f4fmas(w, z1, AP[1]);
        }
        s[0] = f4mul(P[0], AP[0]);
        s[1] = f4mul(P[1], AP[1]);
        block_partials(s, g_part_d);
        gsync(1 + 2*k);
        row_reduce(g_part_d, s_scal);

        // ---- phase 2: alpha ; X += aP ; R -= aAP ; Z = Minv*R ; rz_new = <R,Z> ----
        {
            const float4* rz4 = (const float4*)&s_rzs[k & 1][h*8];
            const float4* dn4 = (const float4*)&s_scal[h*8];
            #pragma unroll
            for (int j = 0; j < 2; j++){
                float4 a = f4div_guard(rz4[j], dn4[j]);
                X[j] = f4fma(a, P[j], X[j]);
                float4 na = make_float4(-a.x,-a.y,-a.z,-a.w);
                R[j] = f4fma(na, AP[j], R[j]);
                float4 z = f4scale(Minv, R[j]);
                __stcg(&g_Z[v*4 + jb + j], z);
                s[j] = f4mul(R[j], z);
            }
        }
        block_partials(s, g_part_r);
        gsync(2 + 2*k);
        row_reduce(g_part_r, s_rzs[(k + 1) & 1]);
    }

    // ---- write U and S ----
    float4* oU = (float4*)outU;
    float4* oS = (float4*)outS;
    #pragma unroll
    for (int j = 0; j < 2; j++){
        __stcg(&oU[v*4 + jb + j], X[j]);
        oS[v*4 + jb + j] = make_float4(safe_log_neg(X[j].x), safe_log_neg(X[j].y),
                                       safe_log_neg(X[j].z), safe_log_neg(X[j].w));
    }
    gsync(81);

    // ---- faces: Xdir (one face per thread, full 16 RHS) ----
    for (int f = gtid; f < NF; f += NV*2){
        int vi = F[f*3], vj = F[f*3+1], vk = F[f*3+2];
        float gix = gI[f*3], giy = gI[f*3+1], giz = gI[f*3+2];
        float gjx = gJ[f*3], gjy = gJ[f*3+1], gjz = gJ[f*3+2];
        float gkx = gK[f*3], gky = gK[f*3+1], gkz = gK[f*3+2];
        float* o = outX + f*48;
        #pragma unroll
        for (int j = 0; j < 4; j++){
            float4 uI = __ldcg(&oU[vi*4 + j]);
            float4 uJ = __ldcg(&oU[vj*4 + j]);
            float4 uK = __ldcg(&oU[vk*4 + j]);
            const float ui[4] = {uI.x, uI.y, uI.z, uI.w};
            const float uj[4] = {uJ.x, uJ.y, uJ.z, uJ.w};
            const float uk[4] = {uK.x, uK.y, uK.z, uK.w};
            #pragma unroll
            for (int c = 0; c < 4; c++){
                float gx = ui[c]*gix + uj[c]*gjx + uk[c]*gkx;
                float gy = ui[c]*giy + uj[c]*gjy + uk[c]*gky;
                float gz = ui[c]*giz + uj[c]*gjz + uk[c]*gkz;
                float n = sqrtf(gx*gx + gy*gy + gz*gz);
                n = fmaxf(n, 1e-12f);
                float inv = -1.0f / n;
                int cc = j*4 + c;
                o[cc*3+0] = gx*inv;
                o[cc*3+1] = gy*inv;
                o[cc*3+2] = gz*inv;
            }
        }
    }
}

extern "C" void kernel_launch(void* const* d_in, const int* in_sizes, int n_in,
                              void* d_out, int out_size) {
    const int*   F   = (const int*)  d_in[0];
    const int*   row = (const int*)  d_in[1];
    const int*   col = (const int*)  d_in[2];
    const float* val = (const float*)d_in[3];
    const float* M   = (const float*)d_in[4];
    const float* gI  = (const float*)d_in[5];
    const float* gJ  = (const float*)d_in[6];
    const float* gK  = (const float*)d_in[7];
    const float* B   = (const float*)d_in[8];
    const float* tp  = (const float*)d_in[9];
    int nnz = in_sizes[1];

    float* out  = (float*)d_out;
    float* outU = out;
    float* outX = out + NV*16;
    float* outS = out + NV*16 + NF*16*3;

    const int dyn_smem = TILE * 4 * sizeof(float4);    // 49280 bytes
    cudaFuncSetAttribute(cg_persist, cudaFuncAttributeMaxDynamicSharedMemorySize, dyn_smem);

    zero_k   <<<(NV*7)/256, 256>>>();
    scatter_k<<<(nnz + 255)/256, 256>>>(row, col, val, nnz);
    cg_persist<<<NBLK, NTHR, dyn_smem>>>(M, B, tp, F, gI, gJ, gK, outU, outX, outS);
}

// round 5
// speedup vs baseline: 1.0388x; 1.0388x over previous
#include <cuda_runtime.h>
#include <math.h>

#define NV    65536
#define ITERS 40
#define NF    130050
#define NBLK  256
#define NTHR  512
#define NTOT  (NBLK*NTHR)     // 131072 = 2 threads per vertex
#define NSYNC 96

// ---- device scratch (no allocations allowed) ----
__device__ __align__(16) float    g_W[NV*7];          // aggregated COO weights (slot 0 = diag)
__device__ __align__(16) float4   g_Z[NV*4];          // Z = Minv*R  (stencil operand)
__device__ __align__(16) float    g_part_d[16*NBLK];  // per-block partials: denom
__device__ __align__(16) float    g_part_r[16*NBLK];  // per-block partials: rz
__device__ unsigned               g_cnt[NSYNC];       // monotone barrier counters (never reset)

// shared scratch (file-scope __shared__: one copy per block)
__shared__ __align__(16) float sm_red[16][16];
__shared__ __align__(16) float s_scal[16];      // denom for current iter
__shared__ __align__(16) float s_rzs[2][16];    // rz ring (cur/prev)

// ---------------- helpers ----------------
__device__ __forceinline__ float4 f4mul(float4 a, float4 b){ return make_float4(a.x*b.x,a.y*b.y,a.z*b.z,a.w*b.w); }
__device__ __forceinline__ float4 f4fma(float4 a, float4 b, float4 c){
    return make_float4(fmaf(a.x,b.x,c.x), fmaf(a.y,b.y,c.y), fmaf(a.z,b.z,c.z), fmaf(a.w,b.w,c.w));
}
__device__ __forceinline__ float4 f4fmas(float s, float4 b, float4 c){
    return make_float4(fmaf(s,b.x,c.x), fmaf(s,b.y,c.y), fmaf(s,b.z,c.z), fmaf(s,b.w,c.w));
}
__device__ __forceinline__ float4 f4scale(float s, float4 a){ return make_float4(s*a.x,s*a.y,s*a.z,s*a.w); }
__device__ __forceinline__ float4 f4div_guard(float4 n, float4 d){
    return make_float4(n.x/fmaxf(d.x,1e-30f), n.y/fmaxf(d.y,1e-30f),
                       n.z/fmaxf(d.z,1e-30f), n.w/fmaxf(d.w,1e-30f));
}

// Monotone grid barrier: counter only increases across replays.
// All NBLK blocks of this replay share the same target because kernel
// launches serialize on the stream (counter == r*NBLK at replay r entry).
__device__ __forceinline__ void gbar(int idx){
    __threadfence();
    __syncthreads();
    if (threadIdx.x == 0){
        unsigned old = atomicAdd(&g_cnt[idx], 1u);
        unsigned target = old - (old % NBLK) + NBLK;
        while (*(volatile unsigned*)&g_cnt[idx] < target) { }
        __threadfence();
    }
    __syncthreads();
}

// Block partial reduce: each thread holds 8 partials (s[0..1]) for RHS range
// h*8..h*8+7, h == (lane & 1). 16 per-RHS partials -> g_part[rhs*NBLK + blk].
__device__ __forceinline__ void block_partials(float4* s, float* gdst){
    #pragma unroll
    for (int m = 2; m < 32; m <<= 1){
        #pragma unroll
        for (int j = 0; j < 2; j++){
            s[j].x += __shfl_xor_sync(0xffffffffu, s[j].x, m);
            s[j].y += __shfl_xor_sync(0xffffffffu, s[j].y, m);
            s[j].z += __shfl_xor_sync(0xffffffffu, s[j].z, m);
            s[j].w += __shfl_xor_sync(0xffffffffu, s[j].w, m);
        }
    }
    int lane = threadIdx.x & 31, wid = threadIdx.x >> 5;
    if (lane < 2){
        float* row = &sm_red[wid][lane*8];
        row[0] = s[0].x; row[1] = s[0].y; row[2] = s[0].z; row[3] = s[0].w;
        row[4] = s[1].x; row[5] = s[1].y; row[6] = s[1].z; row[7] = s[1].w;
    }
    __syncthreads();
    if (threadIdx.x < 16){
        float acc = 0.f;
        #pragma unroll
        for (int w = 0; w < 16; w++) acc += sm_red[w][threadIdx.x];
        gdst[threadIdx.x*NBLK + blockIdx.x] = acc;   // plain store, deterministic
    }
}

// After gbar: every block reduces the 16 rows of g_part into dsm[0..15].
__device__ __forceinline__ void row_reduce(const float* gsrc, float* dsm){
    int wid = threadIdx.x >> 5, lane = threadIdx.x & 31;
    const float4* p = (const float4*)(gsrc + wid*NBLK) + lane*2;
    float4 a = __ldcg(p);
    float4 b = __ldcg(p+1);
    float acc = (a.x+a.y) + (a.z+a.w) + (b.x+b.y) + (b.z+b.w);
    #pragma unroll
    for (int m = 16; m; m >>= 1) acc += __shfl_xor_sync(0xffffffffu, acc, m);
    if (lane == 0) dsm[wid] = acc;
    __syncthreads();
}

__device__ __forceinline__ float safe_log_neg(float u){
    float us = u;
    if (isnan(us))      us = 1e-9f;
    else if (isinf(us)) us = (us > 0.f) ? 1.0f : 0.0f;
    return -logf(fmaxf(us, 1e-9f));
}

// ---------------- single persistent kernel ----------------
// 2 threads per vertex: h = tid&1 owns RHS [h*8, h*8+8)
__global__ void __launch_bounds__(NTHR, 2)
cg_persist(const int* __restrict__ row, const int* __restrict__ col,
           const float* __restrict__ val, int nnz,
           const float* __restrict__ M, const float* __restrict__ B,
           const float* __restrict__ tp,
           const int* __restrict__ F, const float* __restrict__ gI,
           const float* __restrict__ gJ, const float* __restrict__ gK,
           float* __restrict__ outU, float* __restrict__ outX, float* __restrict__ outS)
{
    const int gtid = blockIdx.x * NTHR + threadIdx.x;  // [0, NTOT)

    // ---- A: zero weight table ----
    #pragma unroll
    for (int i = gtid; i < NV*7; i += NTOT) g_W[i] = 0.f;
    gbar(0);

    // ---- B: scatter COO -> 7-slot stencil ----
    for (int e = gtid; e < nnz; e += NTOT){
        int r = row[e];
        int d = col[e] - r;
        int slot;
        if      (d == 0)    slot = 0;
        else if (d == -256) slot = 1;
        else if (d == 256)  slot = 2;
        else if (d == -1)   slot = 3;
        else if (d == 1)    slot = 4;
        else if (d == -257) slot = 5;
        else                slot = 6;   // d == 257
        atomicAdd(&g_W[r*7 + slot], val[e]);
    }
    gbar(1);

    // ---- C: per-vertex weights + CG init ----
    const int v = gtid >> 1;
    const int h = gtid & 1;
    const int jb = h * 2;                              // float4 index base within [0,4)
    const float t = *tp;

    float Dw = M[v] + t * g_W[v*7];
    float Minv = 1.0f / fmaxf(Dw, 1e-12f);
    float offW[6];
    #pragma unroll
    for (int e = 0; e < 6; e++) offW[e] = t * g_W[v*7 + 1 + e];

    float4 X[2], R[2], P[2], AP[2], s[2];
    const float4* B4 = (const float4*)B;
    #pragma unroll
    for (int j = 0; j < 2; j++){
        R[j]  = B4[v*4 + jb + j];
        X[j]  = make_float4(0.f,0.f,0.f,0.f);
        float4 z = f4scale(Minv, R[j]);
        __stcg(&g_Z[v*4 + jb + j], z);
        s[j]  = f4mul(R[j], z);
    }
    block_partials(s, g_part_r);
    gbar(2);
    row_reduce(g_part_r, s_rzs[0]);

    const int off[6] = {-256, 256, -1, 1, -257, 257};

    for (int k = 0; k < ITERS; k++){
        // ---- phase 1: P = Z + beta*P ; AP = A*Z + beta*AP ; denom = <P,AP> ----
        {
            float4 z0 = __ldcg(&g_Z[v*4 + jb]);
            float4 z1 = __ldcg(&g_Z[v*4 + jb + 1]);
            if (k == 0){
                AP[0] = f4scale(Dw, z0);  AP[1] = f4scale(Dw, z1);
                P[0]  = z0;               P[1]  = z1;
            } else {
                const float4* rn = (const float4*)&s_rzs[k & 1][h*8];
                const float4* ro = (const float4*)&s_rzs[(k & 1) ^ 1][h*8];
                float4 bt0 = f4div_guard(rn[0], ro[0]);
                float4 bt1 = f4div_guard(rn[1], ro[1]);
                AP[0] = f4fma(bt0, AP[0], f4scale(Dw, z0));
                AP[1] = f4fma(bt1, AP[1], f4scale(Dw, z1));
                P[0]  = f4fma(bt0, P[0], z0);
                P[1]  = f4fma(bt1, P[1], z1);
            }
        }
        #pragma unroll
        for (int e = 0; e < 6; e++){
            int nb = v + off[e];
            nb = max(0, min(NV-1, nb));      // absent-edge weight is exactly 0
            float w = offW[e];
            float4 z0 = __ldcg(&g_Z[nb*4 + jb]);
            float4 z1 = __ldcg(&g_Z[nb*4 + jb + 1]);
            AP[0] = f4fmas(w, z0, AP[0]);
            AP[1] = f4fmas(w, z1, AP[1]);
        }
        s[0] = f4mul(P[0], AP[0]);
        s[1] = f4mul(P[1], AP[1]);
        block_partials(s, g_part_d);
        gbar(3 + 2*k);
        row_reduce(g_part_d, s_scal);

        // ---- phase 2: alpha ; X += aP ; R -= aAP ; Z = Minv*R ; rz_new = <R,Z> ----
        {
            const float4* rz4 = (const float4*)&s_rzs[k & 1][h*8];
            const float4* dn4 = (const float4*)&s_scal[h*8];
            #pragma unroll
            for (int j = 0; j < 2; j++){
                float4 a = f4div_guard(rz4[j], dn4[j]);
                X[j] = f4fma(a, P[j], X[j]);
                float4 na = make_float4(-a.x,-a.y,-a.z,-a.w);
                R[j] = f4fma(na, AP[j], R[j]);
                float4 z = f4scale(Minv, R[j]);
                __stcg(&g_Z[v*4 + jb + j], z);
                s[j] = f4mul(R[j], z);
            }
        }
        block_partials(s, g_part_r);
        gbar(4 + 2*k);
        row_reduce(g_part_r, s_rzs[(k + 1) & 1]);
    }

    // ---- write U and S ----
    float4* oU = (float4*)outU;
    float4* oS = (float4*)outS;
    #pragma unroll
    for (int j = 0; j < 2; j++){
        __stcg(&oU[v*4 + jb + j], X[j]);
        oS[v*4 + jb + j] = make_float4(safe_log_neg(X[j].x), safe_log_neg(X[j].y),
                                       safe_log_neg(X[j].z), safe_log_neg(X[j].w));
    }
    gbar(83);

    // ---- faces: Xdir ----
    for (int f = gtid; f < NF; f += NTOT){
        int vi = F[f*3], vj = F[f*3+1], vk = F[f*3+2];
        float gix = gI[f*3], giy = gI[f*3+1], giz = gI[f*3+2];
        float gjx = gJ[f*3], gjy = gJ[f*3+1], gjz = gJ[f*3+2];
        float gkx = gK[f*3], gky = gK[f*3+1], gkz = gK[f*3+2];
        float* o = outX + f*48;
        #pragma unroll
        for (int j = 0; j < 4; j++){
            float4 uI = __ldcg(&oU[vi*4 + j]);
            float4 uJ = __ldcg(&oU[vj*4 + j]);
            float4 uK = __ldcg(&oU[vk*4 + j]);
            const float ui[4] = {uI.x, uI.y, uI.z, uI.w};
            const float uj[4] = {uJ.x, uJ.y, uJ.z, uJ.w};
            const float uk[4] = {uK.x, uK.y, uK.z, uK.w};
            #pragma unroll
            for (int c = 0; c < 4; c++){
                float gx = ui[c]*gix + uj[c]*gjx + uk[c]*gkx;
                float gy = ui[c]*giy + uj[c]*gjy + uk[c]*gky;
                float gz = ui[c]*giz + uj[c]*gjz + uk[c]*gkz;
                float n = sqrtf(gx*gx + gy*gy + gz*gz);
                n = fmaxf(n, 1e-12f);
                float inv = -1.0f / n;
                int cc = j*4 + c;
                o[cc*3+0] = gx*inv;
                o[cc*3+1] = gy*inv;
                o[cc*3+2] = gz*inv;
            }
        }
    }
}

extern "C" void kernel_launch(void* const* d_in, const int* in_sizes, int n_in,
                              void* d_out, int out_size) {
    const int*   F   = (const int*)  d_in[0];
    const int*   row = (const int*)  d_in[1];
    const int*   col = (const int*)  d_in[2];
    const float* val = (const float*)d_in[3];
    const float* M   = (const float*)d_in[4];
    const float* gI  = (const float*)d_in[5];
    const float* gJ  = (const float*)d_in[6];
    const float* gK  = (const float*)d_in[7];
    const float* B   = (const float*)d_in[8];
    const float* tp  = (const float*)d_in[9];
    int nnz = in_sizes[1];

    float* out  = (float*)d_out;
    float* outU = out;
    float* outX = out + NV*16;
    float* outS = out + NV*16 + NF*16*3;

    cg_persist<<<NBLK, NTHR>>>(row, col, val, nnz, M, B, tp,
                               F, gI, gJ, gK, outU, outX, outS);
}